// round 12
// baseline (speedup 1.0000x reference)
#include <cuda_runtime.h>
#include <cstdint>

#define V_N 65536
#define E_N 4096
#define P_N 4096
#define T_N 512
#define SENTF 1000000000.0f
#define BIGF  1e30f
#define INFF  __int_as_float(0x7f800000)

// Scratch (device globals: no allocations allowed)
__device__ float2 g_passA[E_N];   // (xmn, xmx)
__device__ float4 g_passB[E_N];   // (ymn, ymx, -b*w, w)   w = 1/a
__device__ float2 g_ab[E_N];      // (a, b)
__device__ float4 g_tbl[T_N];     // TableR cols 3..6
__device__ float  g_m[P_N];
__device__ int    g_valid[P_N];
__device__ int    g_done = 0;     // last-block counter (reset by last block)

// Predicated pass-2 update for one (edge q, point i) pair
#define PBODY(q, NN, MX, MN, XSv, XIv, CYv, PXv)                           \
    {                                                                      \
        float xi_ = fmaf((CYv), (q).w, (q).z);                             \
        asm("{\n\t"                                                        \
            ".reg .pred pc, pg, pl;\n\t"                                   \
            "setp.gt.f32 pc, %6, %7;\n\t"                                  \
            "setp.lt.and.f32 pc, %6, %8, pc;\n\t"                          \
            "@pc add.s32 %4, %4, 1;\n\t"                                   \
            "@pc max.f32 %0, %0, %5;\n\t"                                  \
            "@pc min.f32 %1, %1, %5;\n\t"                                  \
            "setp.ge.and.f32 pg, %5, %9, pc;\n\t"                          \
            "setp.lt.and.f32 pl, %5, %9, pc;\n\t"                          \
            "@pg min.f32 %2, %2, %5;\n\t"                                  \
            "@pl max.f32 %3, %3, %5;\n\t"                                  \
            "}"                                                            \
            : "+f"(MX), "+f"(MN), "+f"(XSv), "+f"(XIv), "+r"(NN)           \
            : "f"(xi_), "f"(CYv), "f"((q).x), "f"((q).y), "f"(PXv));       \
    }

#define TBL_BODY(r)                                                        \
    {                                                                      \
        float al = fabsf(L1v - (r).x) + fabsf(L2v - (r).y)                 \
                 + fabsf(d1  - (r).z) + fabsf(d2  - (r).w);                \
        pm = fminf(pm, al);                                                \
    }

// ---------------------------------------------------------------------------
// K1: per-edge precompute + table extraction
// ---------------------------------------------------------------------------
__global__ void __launch_bounds__(64) prep_kernel(
        const float* __restrict__ verts,
        const float* __restrict__ tableR,
        const int*   __restrict__ edges) {
    int e = blockIdx.x * blockDim.x + threadIdx.x;
    if (e < T_N) {
        const float* r = tableR + e * 7;
        g_tbl[e] = make_float4(r[3], r[4], r[5], r[6]);
    }
    if (e < E_N) {
        int i0 = edges[2 * e + 0];
        int i1 = edges[2 * e + 1];
        float x0 = verts[3 * i0 + 0], y0 = verts[3 * i0 + 1];
        float x1 = verts[3 * i1 + 0], y1 = verts[3 * i1 + 1];
        float a = (y0 - y1) / (x0 - x1);                 // IEEE div (matches ref)
        float b = __fsub_rn(y0, __fmul_rn(a, x0));       // no FMA contraction
        float w = 1.0f / a;
        float nbw = -__fmul_rn(b, w);                    // xi = fma(cy, w, nbw)
        g_passA[e] = make_float2(fminf(x0, x1), fmaxf(x0, x1));
        g_passB[e] = make_float4(fminf(y0, y1), fmaxf(y0, y1), nbw, w);
        g_ab[e]    = make_float2(a, b);
    }
}

// ---------------------------------------------------------------------------
// K2: warp-cooperative points.
//     Block = 256 thr = 8 warps = 8 points; 2 groups of 4 warps.
//     Pass-2: each warp streams 1024 edges (its quarter) for ALL 4 points of
//     its group -> total pass-2 LDG.128 count cut 4x at unchanged occupancy.
// ---------------------------------------------------------------------------
__global__ void __launch_bounds__(256, 3) point_kernel(
        const float* __restrict__ verts,
        const int*   __restrict__ listAll,
        float*       __restrict__ out) {
    const unsigned FULL = 0xffffffffu;
    const int tid   = threadIdx.x;
    const int lane  = tid & 31;
    const int warp  = tid >> 5;          // 0..7
    const int group = warp >> 2;         // 0..1
    const int wg    = warp & 3;          // quarter index within group
    const int p_own = blockIdx.x * 8 + warp;

    __shared__ float s_cy[8], s_px[8];
    __shared__ int   s_n [8][4];
    __shared__ float s_mx[8][4], s_mn[8][4], s_xs[8][4], s_xi[8][4];

    // ---- coords + Pass 1 for OWN point ----
    int li = __ldg(&listAll[p_own]);
    float pxo = __ldg(&verts[3 * li + 0]);
    float pyo = __ldg(&verts[3 * li + 1]);

    int idx = 0x7fffffff;
    for (int e = lane; e < E_N; e += 32) {
        float2 mm = __ldg(&g_passA[e]);
        if (pxo > mm.x && pxo < mm.y) { idx = e; break; }  // lane stream ascending
    }
    #pragma unroll
    for (int o = 16; o; o >>= 1)
        idx = min(idx, __shfl_xor_sync(FULL, idx, o));
    if (idx == 0x7fffffff) idx = E_N - 1;

    float2 ab = __ldg(&g_ab[idx]);
    float exposeY = __fadd_rn(__fmul_rn(ab.x, pxo), ab.y);  // no FMA contraction
    float L1v = fabsf(pyo - exposeY);
    float cyo = (pyo + exposeY) * 0.5f;

    if (lane == 0) { s_cy[warp] = cyo; s_px[warp] = pxo; }
    __syncthreads();

    // group's 4 points
    float cy[4], px[4];
    #pragma unroll
    for (int i = 0; i < 4; i++) {
        cy[i] = s_cy[group * 4 + i];
        px[i] = s_px[group * 4 + i];
    }

    // ---- Pass 2: this warp covers edges [wg*1024, wg*1024+1024) ----
    int   n[4];
    float mx[4], mn[4], xs[4], xf[4];
    #pragma unroll
    for (int i = 0; i < 4; i++) {
        n[i] = 0; mx[i] = -SENTF; mn[i] = SENTF; xs[i] = SENTF; xf[i] = -SENTF;
    }
    {
        const float4* __restrict__ pB = g_passB + wg * 1024 + lane;
        #pragma unroll 1
        for (int k = 0; k < 8; k++) {            // 8 batches of 4 loads = 32 iters
            float4 q0 = __ldg(pB +  0);
            float4 q1 = __ldg(pB + 32);
            float4 q2 = __ldg(pB + 64);
            float4 q3 = __ldg(pB + 96);
            pB += 128;
            #pragma unroll
            for (int i = 0; i < 4; i++) PBODY(q0, n[i], mx[i], mn[i], xs[i], xf[i], cy[i], px[i]);
            #pragma unroll
            for (int i = 0; i < 4; i++) PBODY(q1, n[i], mx[i], mn[i], xs[i], xf[i], cy[i], px[i]);
            #pragma unroll
            for (int i = 0; i < 4; i++) PBODY(q2, n[i], mx[i], mn[i], xs[i], xf[i], cy[i], px[i]);
            #pragma unroll
            for (int i = 0; i < 4; i++) PBODY(q3, n[i], mx[i], mn[i], xs[i], xf[i], cy[i], px[i]);
        }
    }
    // intra-warp butterfly per point
    #pragma unroll
    for (int i = 0; i < 4; i++) {
        #pragma unroll
        for (int o = 16; o; o >>= 1) {
            n[i]  +=            __shfl_xor_sync(FULL, n[i],  o);
            mx[i] = fmaxf(mx[i], __shfl_xor_sync(FULL, mx[i], o));
            mn[i] = fminf(mn[i], __shfl_xor_sync(FULL, mn[i], o));
            xs[i] = fminf(xs[i], __shfl_xor_sync(FULL, xs[i], o));
            xf[i] = fmaxf(xf[i], __shfl_xor_sync(FULL, xf[i], o));
        }
    }
    if (lane == 0) {
        #pragma unroll
        for (int i = 0; i < 4; i++) {
            s_n [warp][i] = n[i];
            s_mx[warp][i] = mx[i]; s_mn[warp][i] = mn[i];
            s_xs[warp][i] = xs[i]; s_xi[warp][i] = xf[i];
        }
    }
    __syncthreads();

    // ---- combine 4 quarters for OWN point (index wg within group) ----
    int   N_ = 0;
    float MX = -SENTF, MN = SENTF, XS = SENTF, XF = -SENTF;
    {
        const int iw = warp & 3;         // own point's slot within its group
        #pragma unroll
        for (int u = 0; u < 4; u++) {
            int wq = group * 4 + u;
            N_ += s_n[wq][iw];
            MX = fmaxf(MX, s_mx[wq][iw]);
            MN = fminf(MN, s_mn[wq][iw]);
            XS = fminf(XS, s_xs[wq][iw]);
            XF = fmaxf(XF, s_xi[wq][iw]);
        }
    }

    // condB => xi in [0,1]; presence <=> sentinel moved
    int hs = XS <  SENTF;
    int hi = XF > -SENTF;
    int valid = (N_ == 2) || (N_ > 2 && hs && hi);
    float dx  = (N_ == 2) ? (MX - MN) : (XS - XF);
    float L2v = fabsf(dx);
    float d1  = fabsf(cyo - 1.0f);
    float d2  = fabsf(pxo - 1.0f);

    // ---- Table min for OWN point: 4 batches of 4 loads ----
    float pm = INFF;
    {
        const float4* __restrict__ pT = g_tbl + lane;
        #pragma unroll 1
        for (int k = 0; k < T_N / 128; k++) {
            float4 r0 = __ldg(pT +  0);
            float4 r1 = __ldg(pT + 32);
            float4 r2 = __ldg(pT + 64);
            float4 r3 = __ldg(pT + 96);
            pT += 128;
            TBL_BODY(r0); TBL_BODY(r1); TBL_BODY(r2); TBL_BODY(r3);
        }
    }
    #pragma unroll
    for (int o = 16; o; o >>= 1)
        pm = fminf(pm, __shfl_xor_sync(FULL, pm, o));

    if (lane == 0) {
        g_m[p_own]     = valid ? pm : BIGF;
        g_valid[p_own] = valid;
    }

    // ================== fused scan: last-finishing block ==================
    __shared__ int s_last;
    __threadfence();
    __syncthreads();
    if (tid == 0) {
        int old = atomicAdd(&g_done, 1);
        s_last = (old == (int)gridDim.x - 1);
    }
    __syncthreads();
    if (!s_last) return;

    {
        __shared__ float s_wtot[8];
        __shared__ float s_sum[8];
        const int base = tid * 16;       // 256 threads * 16 values

        float c[16];
        float run = INFF;
        #pragma unroll
        for (int i = 0; i < 16; i++) {
            run = fminf(run, g_m[base + i]);
            c[i] = run;
        }

        float scan = run;
        #pragma unroll
        for (int o = 1; o < 32; o <<= 1) {
            float v = __shfl_up_sync(FULL, scan, o);
            if (lane >= o) scan = fminf(scan, v);
        }
        if (lane == 31) s_wtot[warp] = scan;
        __syncthreads();

        float wpre = INFF;
        #pragma unroll
        for (int w = 0; w < 8; w++)
            if (w < warp) wpre = fminf(wpre, s_wtot[w]);

        float lpre = __shfl_up_sync(FULL, scan, 1);
        float pre = fminf(wpre, (lane == 0) ? INFF : lpre);

        float acc = 0.0f;
        #pragma unroll
        for (int i = 0; i < 16; i++)
            if (g_valid[base + i]) acc += fminf(pre, c[i]);

        #pragma unroll
        for (int o = 16; o; o >>= 1)
            acc += __shfl_xor_sync(FULL, acc, o);
        if (lane == 0) s_sum[warp] = acc;
        __syncthreads();
        if (tid == 0) {
            float s = 0.0f;
            #pragma unroll
            for (int w = 0; w < 8; w++) s += s_sum[w];
            out[0] = s;
            g_done = 0;                   // reset for next graph replay
        }
    }
}

// ---------------------------------------------------------------------------
extern "C" void kernel_launch(void* const* d_in, const int* in_sizes, int n_in,
                              void* d_out, int out_size) {
    const float* verts   = (const float*)d_in[0];
    const float* tableR  = (const float*)d_in[1];
    const int*   edges   = (const int*)  d_in[2];
    const int*   listAll = (const int*)  d_in[3];

    prep_kernel <<<64,   64>>>(verts, tableR, edges);
    point_kernel<<<512, 256>>>(verts, listAll, (float*)d_out);
}